// round 11
// baseline (speedup 1.0000x reference)
#include <cuda_runtime.h>
#include <cstdint>

#define HH 400
#define WW 400
#define CC 128
#define KS 25
#define PP 12
#define NPIX (HH*WW)

typedef unsigned long long u64t;

// ---------------- device scratch ----------------
__device__ float g_cubeT[(size_t)CC * NPIX + 1024];   // channel-major transpose (+pad)
__device__ float g_norm[NPIX + 64];
__device__ unsigned int g_max_u;

// ---------------- packed f32x2 helpers (sm_100+ family PTX, not 'a'-gated) ----------------
__device__ __forceinline__ void ffma2(u64t &d, u64t a, u64t b) {
    asm("fma.rn.f32x2 %0, %1, %2, %0;" : "+l"(d) : "l"(a), "l"(b));
}
__device__ __forceinline__ u64t pack2(float lo, float hi) {
    u64t r; asm("mov.b64 %0, {%1, %2};" : "=l"(r) : "f"(lo), "f"(hi)); return r;
}
__device__ __forceinline__ void unpack2(u64t v, float &lo, float &hi) {
    asm("mov.b64 {%0, %1}, %2;" : "=f"(lo), "=f"(hi) : "l"(v));
}

// ---------------- helpers ----------------
__device__ __forceinline__ float kweight(int i, int j) {
    int ii = min(i, 24 - i);
    if (j < 12) return (float)(j - 12 - ii);
    if (j > 12) return (float)(j - 12 + ii);
    return 0.0f;
}

__device__ __forceinline__ float acos_poly(float x) {
    float ax = fabsf(x);
    float p = fmaf(ax, -0.0012624911f, 0.0066700901f);
    p = fmaf(p, ax, -0.0170881256f);
    p = fmaf(p, ax,  0.0308918810f);
    p = fmaf(p, ax, -0.0501743046f);
    p = fmaf(p, ax,  0.0889789874f);
    p = fmaf(p, ax, -0.2145988016f);
    p = fmaf(p, ax,  1.5707963050f);
    float om = 1.0f - ax;
    float s;
    asm("sqrt.approx.f32 %0, %1;" : "=f"(s) : "f"(om));
    float t = s * p;
    return (x < 0.0f) ? (3.14159265358979f - t) : t;
}

// ---------------- K1: transpose pixel-major -> channel-major ----------------
__global__ void k_transpose(const float* __restrict__ cube) {
    __shared__ float tile[32][CC + 4];
    int px0 = blockIdx.x * 32;
    int t = threadIdx.x;
    {
        int lp = t >> 3;
        int cb = (t & 7) << 4;
        const float4* src = reinterpret_cast<const float4*>(cube + (size_t)(px0 + lp) * CC + cb);
        #pragma unroll
        for (int q = 0; q < 4; q++) {
            float4 v = src[q];
            tile[lp][cb + 4*q + 0] = v.x;
            tile[lp][cb + 4*q + 1] = v.y;
            tile[lp][cb + 4*q + 2] = v.z;
            tile[lp][cb + 4*q + 3] = v.w;
        }
    }
    __syncthreads();
    int lane = t & 31;
    int crow = t >> 5;
    #pragma unroll
    for (int it = 0; it < 16; it++) {
        int c = it * 8 + crow;
        g_cubeT[(size_t)c * NPIX + px0 + lane] = tile[lane][c];
    }
    if (blockIdx.x == 0 && t == 0) g_max_u = 0u;
}

// ---------------- K2: per-pixel norms ----------------
__global__ void k_norm() {
    int px = blockIdx.x * blockDim.x + threadIdx.x;
    if (px >= NPIX) return;
    float s = 0.0f;
    #pragma unroll 8
    for (int c = 0; c < CC; c++) {
        float v = g_cubeT[(size_t)c * NPIX + px];
        s = fmaf(v, v, s);
    }
    g_norm[px] = sqrtf(s);
}

// ---------------- K3: main edge kernel (packed f32x2 inner loop) ----------------
// Grid: (3, 47). CTA: 256 threads = 8 warps; warp = tile row; lane = 4 consecutive cols.
__global__ void __launch_bounds__(256, 1) k_edge(float* __restrict__ out) {
    __shared__ float skx[KS*KS], sky[KS*KS];
    __shared__ unsigned int blkmax;
    int t = threadIdx.x;
    if (t == 0) blkmax = 0u;
    for (int i = t; i < KS*KS; i += 256) {
        int di = i / KS, dj = i % KS;
        skx[i] = kweight(di, dj);
        sky[i] = kweight(dj, di);
    }
    __syncthreads();

    int wrp = t >> 5;
    int tx  = t & 31;
    int r   = 12 + blockIdx.y * 8 + wrp;
    int cb  = 12 + blockIdx.x * 128 + tx * 4;
    bool valid = (cb + 3) <= 387;

    float4 nc4 = *reinterpret_cast<const float4*>(&g_norm[r * WW + cb]);
    float ncv[4] = {nc4.x, nc4.y, nc4.z, nc4.w};

    float gx[4] = {0,0,0,0};
    float gy[4] = {0,0,0,0};

    const float* __restrict__ bc = g_cubeT + (size_t)r * WW + cb;

    #pragma unroll 1
    for (int di = 0; di < KS; di++) {
        int srow = r + di - 12;
        const float* __restrict__ bs = g_cubeT + (size_t)srow * WW + (cb - 12);

        // packed accumulators: acc01[dj] = (acc[px0][dj], acc[px1][dj]), acc23 likewise
        u64t acc01[KS], acc23[KS];
        #pragma unroll
        for (int dj = 0; dj < KS; dj++) { acc01[dj] = 0ull; acc23[dj] = 0ull; }

        #pragma unroll 1
        for (int c = 0; c < CC; c++) {
            size_t coff = (size_t)c * NPIX;
            float4 ct4 = *reinterpret_cast<const float4*>(bc + coff);
            u64t a01 = pack2(ct4.x, ct4.y);
            u64t a23 = pack2(ct4.z, ct4.w);

            float s[28];
            #pragma unroll
            for (int j = 0; j < 7; j++) {
                float4 v = *reinterpret_cast<const float4*>(bs + coff + 4*j);
                s[4*j + 0] = v.x; s[4*j + 1] = v.y; s[4*j + 2] = v.z; s[4*j + 3] = v.w;
            }
            // packed window pairs sp[j] = (s[j], s[j+1]), j = 0..26
            u64t sp[27];
            #pragma unroll
            for (int j = 0; j < 27; j++) sp[j] = pack2(s[j], s[j+1]);

            #pragma unroll
            for (int dj = 0; dj < KS; dj++) {
                ffma2(acc01[dj], a01, sp[dj]);      // (px0,px1) x (s[dj],s[dj+1])
                ffma2(acc23[dj], a23, sp[dj + 2]);  // (px2,px3) x (s[dj+2],s[dj+3])
            }
        }

        // epilogue for this di
        const float* __restrict__ nrow = g_norm + (size_t)srow * WW + (cb - 12);
        float ns[28];
        #pragma unroll
        for (int j = 0; j < 7; j++) {
            float4 v = *reinterpret_cast<const float4*>(nrow + 4*j);
            ns[4*j + 0] = v.x; ns[4*j + 1] = v.y; ns[4*j + 2] = v.z; ns[4*j + 3] = v.w;
        }
        #pragma unroll
        for (int dj = 0; dj < KS; dj++) {
            float kxv = skx[di*KS + dj];
            float kyv = sky[di*KS + dj];
            float a[4];
            unpack2(acc01[dj], a[0], a[1]);
            unpack2(acc23[dj], a[2], a[3]);
            #pragma unroll
            for (int p = 0; p < 4; p++) {
                float den = fmaf(ncv[p], ns[p + dj], 1e-4f);
                float ratio = __fdividef(a[p], den);
                ratio = fminf(fmaxf(ratio, -1.0f + 1e-6f), 1.0f - 1e-6f);
                float sad = acos_poly(ratio);
                gx[p] = fmaf(sad, kxv, gx[p]);
                gy[p] = fmaf(sad, kyv, gy[p]);
            }
        }
    }

    if (valid) {
        float4 e;
        e.x = fabsf(gx[0]) + fabsf(gy[0]);
        e.y = fabsf(gx[1]) + fabsf(gy[1]);
        e.z = fabsf(gx[2]) + fabsf(gy[2]);
        e.w = fabsf(gx[3]) + fabsf(gy[3]);
        *reinterpret_cast<float4*>(out + (size_t)r * WW + cb) = e;
        float m = fmaxf(fmaxf(e.x, e.y), fmaxf(e.z, e.w));
        atomicMax(&blkmax, __float_as_uint(m));
    }
    __syncthreads();
    if (t == 0) atomicMax(&g_max_u, blkmax);
}

// ---------------- K4: normalize + zero border ----------------
__global__ void k_final(float* __restrict__ out) {
    int idx = blockIdx.x * blockDim.x + threadIdx.x;
    if (idx >= NPIX) return;
    int h = idx / WW;
    int w = idx - h * WW;
    float m = __uint_as_float(g_max_u);
    if (h >= 12 && h < 388 && w >= 12 && w < 388) {
        out[idx] = out[idx] / m;
    } else {
        out[idx] = 0.0f;
    }
}

// ---------------- launch ----------------
extern "C" void kernel_launch(void* const* d_in, const int* in_sizes, int n_in,
                              void* d_out, int out_size) {
    const float* cube = (const float*)d_in[0];
    float* out = (float*)d_out;

    k_transpose<<<NPIX / 32, 256>>>(cube);
    k_norm<<<(NPIX + 255) / 256, 256>>>();
    {
        dim3 grid(3, 47);
        k_edge<<<grid, 256>>>(out);
    }
    k_final<<<(NPIX + 255) / 256, 256>>>(out);
}

// round 14
// speedup vs baseline: 1.6697x; 1.6697x over previous
#include <cuda_runtime.h>
#include <cstdint>

#define HH 400
#define WW 400
#define CC 128
#define KS 25
#define NPIX (HH*WW)

typedef unsigned long long u64t;

__device__ float g_cubeT[(size_t)CC * NPIX + 1024];
__device__ float g_norm[NPIX + 64];
__device__ unsigned int g_max_u;

// ---------------- asm helpers ----------------
__device__ __forceinline__ uint32_t smem_u32(const void* p) {
    uint32_t a;
    asm("{ .reg .u64 t; cvta.to.shared.u64 t, %1; cvt.u32.u64 %0, t; }" : "=r"(a) : "l"(p));
    return a;
}
__device__ __forceinline__ void cp16(uint32_t dst, const float* src) {
    asm volatile("cp.async.ca.shared.global [%0], [%1], 16;" :: "r"(dst), "l"(src));
}
__device__ __forceinline__ void cp_commit() {
    asm volatile("cp.async.commit_group;" ::: "memory");
}
__device__ __forceinline__ void cp_wait1() {
    asm volatile("cp.async.wait_group 1;" ::: "memory");
}
__device__ __forceinline__ void cp_wait0() {
    asm volatile("cp.async.wait_group 0;" ::: "memory");
}
__device__ __forceinline__ void lds2u64(u64t &a, u64t &b, uint32_t addr) {
    asm volatile("ld.shared.v2.u64 {%0,%1}, [%2];" : "=l"(a), "=l"(b) : "r"(addr));
}
__device__ __forceinline__ void lds4f(float &x, float &y, float &z, float &w, uint32_t addr) {
    asm volatile("ld.shared.v4.f32 {%0,%1,%2,%3}, [%4];" : "=f"(x), "=f"(y), "=f"(z), "=f"(w) : "r"(addr));
}
__device__ __forceinline__ void ffma2(u64t &d, u64t a, u64t b) {
    asm("fma.rn.f32x2 %0, %1, %2, %0;" : "+l"(d) : "l"(a), "l"(b));
}
__device__ __forceinline__ u64t bcast2(float x) {
    u64t r; asm("mov.b64 %0, {%1, %1};" : "=l"(r) : "f"(x)); return r;
}
__device__ __forceinline__ void unpk(u64t v, float &lo, float &hi) {
    asm("mov.b64 {%0, %1}, %2;" : "=f"(lo), "=f"(hi) : "l"(v));
}

__device__ __forceinline__ float kweight(int i, int j) {
    int ii = min(i, 24 - i);
    if (j < 12) return (float)(j - 12 - ii);
    if (j > 12) return (float)(j - 12 + ii);
    return 0.0f;
}
__device__ __forceinline__ float acos_poly(float x) {
    float ax = fabsf(x);
    float p = fmaf(ax, -0.0012624911f, 0.0066700901f);
    p = fmaf(p, ax, -0.0170881256f);
    p = fmaf(p, ax,  0.0308918810f);
    p = fmaf(p, ax, -0.0501743046f);
    p = fmaf(p, ax,  0.0889789874f);
    p = fmaf(p, ax, -0.2145988016f);
    p = fmaf(p, ax,  1.5707963050f);
    float om = 1.0f - ax;
    float s;
    asm("sqrt.approx.f32 %0, %1;" : "=f"(s) : "f"(om));
    float t = s * p;
    return (x < 0.0f) ? (3.14159265358979f - t) : t;
}

// ---------------- K1: transpose ----------------
__global__ void k_transpose(const float* __restrict__ cube) {
    __shared__ float tile[32][CC + 4];
    int px0 = blockIdx.x * 32;
    int t = threadIdx.x;
    {
        int lp = t >> 3;
        int cbk = (t & 7) << 4;
        const float4* src = reinterpret_cast<const float4*>(cube + (size_t)(px0 + lp) * CC + cbk);
        #pragma unroll
        for (int q = 0; q < 4; q++) {
            float4 v = src[q];
            tile[lp][cbk + 4*q + 0] = v.x;
            tile[lp][cbk + 4*q + 1] = v.y;
            tile[lp][cbk + 4*q + 2] = v.z;
            tile[lp][cbk + 4*q + 3] = v.w;
        }
    }
    __syncthreads();
    int lane = t & 31;
    int crow = t >> 5;
    #pragma unroll
    for (int it = 0; it < 16; it++) {
        int c = it * 8 + crow;
        g_cubeT[(size_t)c * NPIX + px0 + lane] = tile[lane][c];
    }
    if (blockIdx.x == 0 && t == 0) g_max_u = 0u;
}

// ---------------- K2: norms ----------------
__global__ void k_norm() {
    int px = blockIdx.x * blockDim.x + threadIdx.x;
    if (px >= NPIX) return;
    float s = 0.0f;
    #pragma unroll 8
    for (int c = 0; c < CC; c++) {
        float v = g_cubeT[(size_t)c * NPIX + px];
        s = fmaf(v, v, s);
    }
    g_norm[px] = sqrtf(s);
}

// ---------------- K3: main kernel: smem-staged + f32x2 ----------------
// grid (3,47), 256 thr; warp = row, lane = 4 px. Stage window(160f)+center(128f)
// per (warp, c) via cp.async, triple-buffered; consume via ld.shared.v2.u64.
__global__ void __launch_bounds__(256, 1) k_edge(float* __restrict__ out) {
    __shared__ float s_stage[3][8][288];   // [buf][warp][160 win + 128 ctr]
    __shared__ float skx[KS*KS], sky[KS*KS];
    __shared__ unsigned int blkmax;

    int t = threadIdx.x;
    if (t == 0) blkmax = 0u;
    for (int i = t; i < KS*KS; i += 256) {
        int di = i / KS, dj = i % KS;
        skx[i] = kweight(di, dj);
        sky[i] = kweight(dj, di);
    }
    __syncthreads();

    const int w  = t >> 5;
    const int L  = t & 31;
    const int bx = blockIdx.x;
    const int r  = 12 + blockIdx.y * 8 + w;
    const int cb = 12 + bx * 128 + L * 4;
    const bool valid = (cb + 3) <= 387;

    // smem addresses for this lane (stage dst == read base: float offset 4L)
    uint32_t wdst[3], cdst[3];
    {
        uint32_t sb = smem_u32(&s_stage[0][0][0]);
        #pragma unroll
        for (int b = 0; b < 3; b++) {
            wdst[b] = sb + (uint32_t)(((b*8 + w)*288 + 4*L) * 4);
            cdst[b] = sb + (uint32_t)(((b*8 + w)*288 + 160 + 4*L) * 4);
        }
    }
    const float* ctr0 = g_cubeT + (size_t)r * WW + 12 + bx * 128 + 4*L;

    float4 nc4 = *reinterpret_cast<const float4*>(&g_norm[r * WW + cb]);
    float ncv[4] = {nc4.x, nc4.y, nc4.z, nc4.w};
    float gx[4] = {0,0,0,0};
    float gy[4] = {0,0,0,0};

    #pragma unroll 1
    for (int di = 0; di < KS; di++) {
        int srow = r + di - 12;
        const float* ws = g_cubeT + (size_t)srow * WW + bx * 128 + 4*L;
        const float* cs = ctr0;

        // prologue: stage c=0 into buf 0
        cp16(wdst[0], ws);
        if (L < 8) cp16(wdst[0] + 512, ws + 128);
        cp16(cdst[0], cs);
        cp_commit();
        ws += NPIX; cs += NPIX;

        // packed accumulators (pair mapping verified against acc[p][dj]=sum ctr[p]*s[p+dj])
        u64t ap0[12], ap1[12], ap2[12], ap3[12];
        float a0s = 0.f, a1s = 0.f, a2s = 0.f, a3s = 0.f;
        #pragma unroll
        for (int j = 0; j < 12; j++) { ap0[j]=0ull; ap1[j]=0ull; ap2[j]=0ull; ap3[j]=0ull; }

        #pragma unroll 2
        for (int c = 0; c < CC; c++) {
            int buf = c % 3;
            if (c < CC-1) {
                int nb = (c+1) % 3;
                cp16(wdst[nb], ws);
                if (L < 8) cp16(wdst[nb] + 512, ws + 128);
                cp16(cdst[nb], cs);
                cp_commit();
                ws += NPIX; cs += NPIX;
                cp_wait1();
            } else {
                cp_wait0();
            }
            __syncwarp();

            u64t e[14];
            #pragma unroll
            for (int j = 0; j < 7; j++)
                lds2u64(e[2*j], e[2*j+1], wdst[buf] + 16*j);
            float c0, c1, c2, c3;
            lds4f(c0, c1, c2, c3, cdst[buf]);

            u64t a0 = bcast2(c0), a1 = bcast2(c1), a2 = bcast2(c2), a3 = bcast2(c3);
            float s0d, s1, s2d, s3, s24, s25d, s26, s27d;
            unpk(e[0], s0d, s1);
            unpk(e[1], s2d, s3);
            unpk(e[12], s24, s25d);
            unpk(e[13], s26, s27d);

            #pragma unroll
            for (int j = 0; j < 12; j++) {
                ffma2(ap0[j], a0, e[j]);       // acc[0][2j,2j+1]   * (s[2j],s[2j+1])
                ffma2(ap1[j], a1, e[j+1]);     // acc[1][2j+1,2j+2] * (s[2j+2],s[2j+3])
                ffma2(ap2[j], a2, e[j+1]);     // acc[2][2j,2j+1]   * (s[2j+2],s[2j+3])
                ffma2(ap3[j], a3, e[j+2]);     // acc[3][2j+1,2j+2] * (s[2j+4],s[2j+5])
            }
            a0s = fmaf(c0, s24, a0s);          // acc[0][24] * s[24]
            a1s = fmaf(c1, s1,  a1s);          // acc[1][0]  * s[1]
            a2s = fmaf(c2, s26, a2s);          // acc[2][24] * s[26]
            a3s = fmaf(c3, s3,  a3s);          // acc[3][0]  * s[3]
        }

        // unpack accs
        float A0[KS], A1[KS], A2[KS], A3[KS];
        #pragma unroll
        for (int j = 0; j < 12; j++) {
            unpk(ap0[j], A0[2*j],   A0[2*j+1]);
            unpk(ap1[j], A1[2*j+1], A1[2*j+2]);
            unpk(ap2[j], A2[2*j],   A2[2*j+1]);
            unpk(ap3[j], A3[2*j+1], A3[2*j+2]);
        }
        A0[24] = a0s; A1[0] = a1s; A2[24] = a2s; A3[0] = a3s;

        // epilogue
        const float* nrow = g_norm + (size_t)srow * WW + bx*128 + 4*L;
        float ns[28];
        #pragma unroll
        for (int j = 0; j < 7; j++) {
            float4 v = *reinterpret_cast<const float4*>(nrow + 4*j);
            ns[4*j+0] = v.x; ns[4*j+1] = v.y; ns[4*j+2] = v.z; ns[4*j+3] = v.w;
        }
        #pragma unroll
        for (int dj = 0; dj < KS; dj++) {
            float kxv = skx[di*KS + dj];
            float kyv = sky[di*KS + dj];
            float a[4] = { A0[dj], A1[dj], A2[dj], A3[dj] };
            #pragma unroll
            for (int p = 0; p < 4; p++) {
                float den = fmaf(ncv[p], ns[p + dj], 1e-4f);
                float ratio = __fdividef(a[p], den);
                ratio = fminf(fmaxf(ratio, -1.0f + 1e-6f), 1.0f - 1e-6f);
                float sad = acos_poly(ratio);
                gx[p] = fmaf(sad, kxv, gx[p]);
                gy[p] = fmaf(sad, kyv, gy[p]);
            }
        }
        __syncwarp();   // all lanes done with this di's buffers before next di restages
    }

    if (valid) {
        float4 e;
        e.x = fabsf(gx[0]) + fabsf(gy[0]);
        e.y = fabsf(gx[1]) + fabsf(gy[1]);
        e.z = fabsf(gx[2]) + fabsf(gy[2]);
        e.w = fabsf(gx[3]) + fabsf(gy[3]);
        *reinterpret_cast<float4*>(out + (size_t)r * WW + cb) = e;
        float m = fmaxf(fmaxf(e.x, e.y), fmaxf(e.z, e.w));
        atomicMax(&blkmax, __float_as_uint(m));
    }
    __syncthreads();
    if (t == 0) atomicMax(&g_max_u, blkmax);
}

// ---------------- K4: normalize + zero border ----------------
__global__ void k_final(float* __restrict__ out) {
    int idx = blockIdx.x * blockDim.x + threadIdx.x;
    if (idx >= NPIX) return;
    int h = idx / WW;
    int ww = idx - h * WW;
    float m = __uint_as_float(g_max_u);
    if (h >= 12 && h < 388 && ww >= 12 && ww < 388) {
        out[idx] = out[idx] / m;
    } else {
        out[idx] = 0.0f;
    }
}

// ---------------- launch ----------------
extern "C" void kernel_launch(void* const* d_in, const int* in_sizes, int n_in,
                              void* d_out, int out_size) {
    const float* cube = (const float*)d_in[0];
    float* out = (float*)d_out;

    k_transpose<<<NPIX / 32, 256>>>(cube);
    k_norm<<<(NPIX + 255) / 256, 256>>>();
    {
        dim3 grid(3, 47);
        k_edge<<<grid, 256>>>(out);
    }
    k_final<<<(NPIX + 255) / 256, 256>>>(out);
}